// round 2
// baseline (speedup 1.0000x reference)
#include <cuda_runtime.h>

// bg: (1, 4, 32, 32, 32, 16) float32  -> d_in[0], 2,097,152 elems
// gm: (1, 1, 128, 128, 128) float32   -> d_in[1], 2,097,152 elems
// out: (1, 4, 128, 128, 128) float32  -> 8,388,608 elems

#define BH 32   // grid h
#define BW 32   // grid w
#define BD 32   // grid d
#define UP 16   // grid "up" (t) dim
#define NC 4    // channels
#define G  128  // guidance / output spatial dim

#define NVOX (G * G * G)                 // 2,097,152
#define BG_SPATIAL (BH * BW * BD * UP)   // 524,288

// Scratch: channel-last transposed grid, layout [x][y][z][t][c], c contiguous.
// 32*32*32*16*4 floats = 8.39 MB. Static device global (no allocation).
__device__ float g_bgT[BG_SPATIAL * NC];

// ---------------------------------------------------------------------------
// Kernel 1: transpose (c, x, y, z, t) -> (x, y, z, t, c) so the 4 channels of
// one (corner, t) sample become a single float4 load in the slice kernel.
// ---------------------------------------------------------------------------
__global__ void bgT_transpose_kernel(const float* __restrict__ bg) {
    int idx = blockIdx.x * blockDim.x + threadIdx.x;  // over (x,y,z,t) flat
    if (idx >= BG_SPATIAL) return;
    float4 v;
    v.x = __ldg(&bg[0 * BG_SPATIAL + idx]);
    v.y = __ldg(&bg[1 * BG_SPATIAL + idx]);
    v.z = __ldg(&bg[2 * BG_SPATIAL + idx]);
    v.w = __ldg(&bg[3 * BG_SPATIAL + idx]);
    reinterpret_cast<float4*>(g_bgT)[idx] = v;
}

// ---------------------------------------------------------------------------
// Kernel 2: slice. One thread = one output voxel, all 4 channels.
// Block = 8x8x8 voxel tile (512 threads). Warp = 2x4x4 (gh x gw x gd) box so
// all lanes of a warp fall into ~1-2 grid cells; a cell's whole t-row is
// 256B = 2 L1 lines, so the random-t accesses of the warp collapse onto
// very few lines per LDG (divergence-wavefront fix).
// ---------------------------------------------------------------------------
__global__ __launch_bounds__(512)
void bgrid_slice_kernel(const float* __restrict__ gm, float* __restrict__ out) {
    int tid = threadIdx.x;

    // lane bits (2x4x4 per warp), higher bits extend the 8x8x8 tile
    int ld = (tid & 3)        | (((tid >> 5) & 1) << 2);   // 0..7
    int lw = ((tid >> 2) & 3) | (((tid >> 6) & 1) << 2);   // 0..7
    int lh = ((tid >> 4) & 1) | (((tid >> 7) & 3) << 1);   // 0..7

    int bd = blockIdx.x & 15;          // 16 tiles per axis
    int bw = (blockIdx.x >> 4) & 15;
    int bh = blockIdx.x >> 8;

    int gh = (bh << 3) | lh;
    int gw = (bw << 3) | lw;
    int gd = (bd << 3) | ld;

    int idx = (gh << 14) | (gw << 7) | gd;

    // Match reference exactly: scale = f32(size-1)/f32(gsize-1), mul in f32,
    // clamp to [0, size-1], floor, i1 = min(i0+1, size-1).
    const float s = 31.0f / 127.0f;

    float x = fminf(fmaxf((float)gh * s, 0.0f), 31.0f);
    float y = fminf(fmaxf((float)gw * s, 0.0f), 31.0f);
    float z = fminf(fmaxf((float)gd * s, 0.0f), 31.0f);

    int   x0 = (int)floorf(x);  float fx = x - (float)x0;  int x1 = min(x0 + 1, BH - 1);
    int   y0 = (int)floorf(y);  float fy = y - (float)y0;  int y1 = min(y0 + 1, BW - 1);
    int   z0 = (int)floorf(z);  float fz = z - (float)z0;  int z1 = min(z0 + 1, BD - 1);

    float g = __ldg(&gm[idx]);
    float t = fminf(fmaxf(g * (float)(UP - 1), 0.0f), (float)(UP - 1));
    int   t0 = (int)floorf(t);  float ft = t - (float)t0;  int t1 = min(t0 + 1, UP - 1);
    float wt0 = 1.0f - ft, wt1 = ft;

    int   xi[2] = { x0, x1 };   float wx[2] = { 1.0f - fx, fx };
    int   yi[2] = { y0, y1 };   float wy[2] = { 1.0f - fy, fy };
    int   zi[2] = { z0, z1 };   float wz[2] = { 1.0f - fz, fz };

    const float4* bgT4 = reinterpret_cast<const float4*>(g_bgT);

    float ax = 0.0f, ay = 0.0f, az = 0.0f, aw = 0.0f;

#pragma unroll
    for (int a = 0; a < 2; a++) {
#pragma unroll
        for (int b = 0; b < 2; b++) {
#pragma unroll
            for (int cc = 0; cc < 2; cc++) {
                float w = wx[a] * wy[b] * wz[cc];
                const float4* base =
                    bgT4 + (((xi[a] * BW + yi[b]) * BD + zi[cc]) * UP);
                float4 v0 = __ldg(base + t0);
                float4 v1 = __ldg(base + t1);
                float w0 = w * wt0, w1 = w * wt1;
                ax += w0 * v0.x + w1 * v1.x;
                ay += w0 * v0.y + w1 * v1.y;
                az += w0 * v0.z + w1 * v1.z;
                aw += w0 * v0.w + w1 * v1.w;
            }
        }
    }

    out[idx]             = ax;
    out[idx + NVOX]      = ay;
    out[idx + 2 * NVOX]  = az;
    out[idx + 3 * NVOX]  = aw;
}

extern "C" void kernel_launch(void* const* d_in, const int* in_sizes, int n_in,
                              void* d_out, int out_size) {
    const float* bg = (const float*)d_in[0];
    const float* gm = (const float*)d_in[1];
    float* out = (float*)d_out;

    (void)in_sizes; (void)n_in; (void)out_size;

    bgT_transpose_kernel<<<(BG_SPATIAL + 255) / 256, 256>>>(bg);
    bgrid_slice_kernel<<<4096, 512>>>(gm, out);
}

// round 3
// speedup vs baseline: 1.5588x; 1.5588x over previous
#include <cuda_runtime.h>
#include <cuda_fp16.h>
#include <stdint.h>

// bg: (1, 4, 32, 32, 32, 16) float32  -> d_in[0]
// gm: (1, 1, 128, 128, 128) float32   -> d_in[1]
// out: (1, 4, 128, 128, 128) float32

#define BH 32
#define UP 16
#define G  128
#define NVOX (G * G * G)                 // 2,097,152
#define BG_SPATIAL (32 * 32 * 32 * 16)   // 524,288

// fp16 channel-last grid: [x][y][z][t][c], half4 (8B) per (x,y,z,t). 4.2 MB.
__device__ __half g_bgT_h[BG_SPATIAL * 4];

// ---------------------------------------------------------------------------
// Kernel 1: transpose + fp16 convert. (c,x,y,z,t) -> [x][y][z][t][c] halves.
// ---------------------------------------------------------------------------
__global__ void bgT_transpose_kernel(const float* __restrict__ bg) {
    int idx = blockIdx.x * blockDim.x + threadIdx.x;
    if (idx >= BG_SPATIAL) return;
    float a = __ldg(&bg[0 * BG_SPATIAL + idx]);
    float b = __ldg(&bg[1 * BG_SPATIAL + idx]);
    float c = __ldg(&bg[2 * BG_SPATIAL + idx]);
    float d = __ldg(&bg[3 * BG_SPATIAL + idx]);
    __half2 lo = __floats2half2_rn(a, b);
    __half2 hi = __floats2half2_rn(c, d);
    uint2 v;
    v.x = *reinterpret_cast<uint32_t*>(&lo);
    v.y = *reinterpret_cast<uint32_t*>(&hi);
    reinterpret_cast<uint2*>(g_bgT_h)[idx] = v;
}

// ---------------------------------------------------------------------------
// Kernel 2: slice with smem-staged grid cells.
// Block = 4(gh) x 4(gw) x 32(gd) voxel tile, 512 threads.
// Cells spanned: 3 x 3 x 10. Stage 90 t-rows (16 x half4 each) in smem,
// then 16 x LDS.64 per voxel (8 corners x {t0,t1}).
// ---------------------------------------------------------------------------
#define CZ 10
#define NCELLS (3 * 3 * CZ)   // 90
#define TSTRIDE 17            // half4 slots per row (pad 16->17 for bank spread)

__global__ __launch_bounds__(512)
void bgrid_slice_kernel(const float* __restrict__ gm, float* __restrict__ out) {
    __shared__ uint2 sgrid[NCELLS * TSTRIDE];  // 90*17*8 = 12240 B

    int tid = threadIdx.x;
    int bd = blockIdx.x & 3;           // 4 gd tiles of 32
    int bw = (blockIdx.x >> 2) & 31;   // 32 gw tiles of 4
    int bh = blockIdx.x >> 7;          // 32 gh tiles of 4

    int gh0 = bh << 2, gw0 = bw << 2, gd0 = bd << 5;

    const float s = 31.0f / 127.0f;
    int bx0 = (int)floorf((float)gh0 * s);
    int by0 = (int)floorf((float)gw0 * s);
    int bz0 = (int)floorf((float)gd0 * s);

    // ---- cooperative fill: 90 cells x 16 t-entries of 8B ----
    const uint2* __restrict__ src = reinterpret_cast<const uint2*>(g_bgT_h);
#pragma unroll
    for (int e = tid; e < NCELLS * 16; e += 512) {
        int t    = e & 15;
        int cell = e >> 4;              // (cx*3+cy)*CZ + cz, cz fastest
        int cz   = cell % CZ;
        int cxy  = cell / CZ;
        int cy   = cxy % 3;
        int cx   = cxy / 3;
        int x = min(bx0 + cx, 31);
        int y = min(by0 + cy, 31);
        int z = min(bz0 + cz, 31);
        sgrid[cell * TSTRIDE + t] = src[((x * 32 + y) * 32 + z) * 16 + t];
    }
    __syncthreads();

    // ---- per-voxel interpolation ----
    int ld = tid & 31;            // gd within tile (coalesced lanes)
    int lw = (tid >> 5) & 3;
    int lh = tid >> 7;

    int gh = gh0 + lh, gw = gw0 + lw, gd = gd0 + ld;
    int idx = (gh << 14) | (gw << 7) | gd;

    // exact reference index/weight math (fp32)
    float x = fminf(fmaxf((float)gh * s, 0.0f), 31.0f);
    float y = fminf(fmaxf((float)gw * s, 0.0f), 31.0f);
    float z = fminf(fmaxf((float)gd * s, 0.0f), 31.0f);

    int x0 = (int)floorf(x);  float fx = x - (float)x0;  int x1 = min(x0 + 1, 31);
    int y0 = (int)floorf(y);  float fy = y - (float)y0;  int y1 = min(y0 + 1, 31);
    int z0 = (int)floorf(z);  float fz = z - (float)z0;  int z1 = min(z0 + 1, 31);

    float g = __ldg(&gm[idx]);
    float t = fminf(fmaxf(g * 15.0f, 0.0f), 15.0f);
    int t0 = (int)floorf(t);  float ft = t - (float)t0;  int t1 = min(t0 + 1, UP - 1);
    float wt0 = 1.0f - ft, wt1 = ft;

    int   cxi[2] = { x0 - bx0, x1 - bx0 };  float wx[2] = { 1.0f - fx, fx };
    int   cyi[2] = { y0 - by0, y1 - by0 };  float wy[2] = { 1.0f - fy, fy };
    int   czi[2] = { z0 - bz0, z1 - bz0 };  float wz[2] = { 1.0f - fz, fz };

    float ax = 0.0f, ay = 0.0f, az = 0.0f, aw = 0.0f;

#pragma unroll
    for (int a = 0; a < 2; a++) {
#pragma unroll
        for (int b = 0; b < 2; b++) {
#pragma unroll
            for (int c = 0; c < 2; c++) {
                float w  = wx[a] * wy[b] * wz[c];
                float w0 = w * wt0, w1 = w * wt1;
                const uint2* row =
                    &sgrid[((cxi[a] * 3 + cyi[b]) * CZ + czi[c]) * TSTRIDE];
                uint2 u0 = row[t0];
                uint2 u1 = row[t1];
                __half2 p0lo = *reinterpret_cast<__half2*>(&u0.x);
                __half2 p0hi = *reinterpret_cast<__half2*>(&u0.y);
                __half2 p1lo = *reinterpret_cast<__half2*>(&u1.x);
                __half2 p1hi = *reinterpret_cast<__half2*>(&u1.y);
                float2 f0lo = __half22float2(p0lo);
                float2 f0hi = __half22float2(p0hi);
                float2 f1lo = __half22float2(p1lo);
                float2 f1hi = __half22float2(p1hi);
                ax += w0 * f0lo.x + w1 * f1lo.x;
                ay += w0 * f0lo.y + w1 * f1lo.y;
                az += w0 * f0hi.x + w1 * f1hi.x;
                aw += w0 * f0hi.y + w1 * f1hi.y;
            }
        }
    }

    out[idx]            = ax;
    out[idx + NVOX]     = ay;
    out[idx + 2 * NVOX] = az;
    out[idx + 3 * NVOX] = aw;
}

extern "C" void kernel_launch(void* const* d_in, const int* in_sizes, int n_in,
                              void* d_out, int out_size) {
    const float* bg = (const float*)d_in[0];
    const float* gm = (const float*)d_in[1];
    float* out = (float*)d_out;

    (void)in_sizes; (void)n_in; (void)out_size;

    bgT_transpose_kernel<<<(BG_SPATIAL + 255) / 256, 256>>>(bg);
    bgrid_slice_kernel<<<4096, 512>>>(gm, out);
}

// round 4
// speedup vs baseline: 1.6297x; 1.0455x over previous
#include <cuda_runtime.h>
#include <cuda_fp16.h>
#include <stdint.h>

// bg: (1, 4, 32, 32, 32, 16) float32  -> d_in[0]
// gm: (1, 1, 128, 128, 128) float32   -> d_in[1]
// out: (1, 4, 128, 128, 128) float32

#define UP 16
#define G  128
#define NVOX (G * G * G)                 // 2,097,152
#define BG_SPATIAL (32 * 32 * 32 * 16)   // 524,288

// Paired fp16 grid: entry (x,y,z,t) = 16B {v4[t] as 4 halves, v4[t+1] as 4
// halves (t+1 clamped to 15)}. 8.4 MB static device scratch.
__device__ uint4 g_bgP[BG_SPATIAL];

// ---------------------------------------------------------------------------
// Kernel 1: transpose (c,x,y,z,t) -> paired channel-last fp16.
// t is the fastest dim and 16 | 32, so lane groups of 16 align with t-rows;
// __shfl_down(width=16) fetches the t+1 entry (lane t=15 keeps its own value
// = the clamp we need).
// ---------------------------------------------------------------------------
__global__ void bgT_pair_kernel(const float* __restrict__ bg) {
    int idx = blockIdx.x * blockDim.x + threadIdx.x;
    if (idx >= BG_SPATIAL) return;
    float a = __ldg(&bg[0 * BG_SPATIAL + idx]);
    float b = __ldg(&bg[1 * BG_SPATIAL + idx]);
    float c = __ldg(&bg[2 * BG_SPATIAL + idx]);
    float d = __ldg(&bg[3 * BG_SPATIAL + idx]);
    __half2 lo = __floats2half2_rn(a, b);
    __half2 hi = __floats2half2_rn(c, d);
    uint32_t ulo = *reinterpret_cast<uint32_t*>(&lo);
    uint32_t uhi = *reinterpret_cast<uint32_t*>(&hi);
    // neighbor (t+1) within 16-lane segment; out-of-segment returns own value
    uint32_t nlo = __shfl_down_sync(0xffffffffu, ulo, 1, 16);
    uint32_t nhi = __shfl_down_sync(0xffffffffu, uhi, 1, 16);
    uint4 e;
    e.x = ulo; e.y = uhi; e.z = nlo; e.w = nhi;
    g_bgP[idx] = e;
}

// ---------------------------------------------------------------------------
// Kernel 2: slice. Block = 4(gh) x 4(gw) x 32(gd) tile, 512 threads.
// Cells spanned: 3 x 3 x 10 = 90. Stage 90 t-rows of paired 16B entries,
// then per voxel: 8 corners x 1 LDS.128, fp16 t-lerp, fp32 spatial accum.
// ---------------------------------------------------------------------------
#define CZ 10
#define NCELLS (3 * 3 * CZ)   // 90
#define TSTRIDE 17            // uint4 slots per row (pad 16->17: rows shift banks)

__global__ __launch_bounds__(512)
void bgrid_slice_kernel(const float* __restrict__ gm, float* __restrict__ out) {
    __shared__ uint4 sgrid[NCELLS * TSTRIDE];  // 90*17*16 = 24480 B

    int tid = threadIdx.x;
    int bd = blockIdx.x & 3;           // 4 gd tiles of 32
    int bw = (blockIdx.x >> 2) & 31;   // 32 gw tiles of 4
    int bh = blockIdx.x >> 7;          // 32 gh tiles of 4

    int gh0 = bh << 2, gw0 = bw << 2, gd0 = bd << 5;

    const float s = 31.0f / 127.0f;
    int bx0 = (int)floorf((float)gh0 * s);
    int by0 = (int)floorf((float)gw0 * s);
    int bz0 = (int)floorf((float)gd0 * s);

    // ---- cooperative fill: 90 cells x 16 paired entries of 16B ----
    for (int e = tid; e < NCELLS * 16; e += 512) {
        int t    = e & 15;
        int cell = e >> 4;              // (cx*3+cy)*CZ + cz
        int cz   = cell % CZ;
        int cxy  = cell / CZ;
        int cy   = cxy % 3;
        int cx   = cxy / 3;
        int x = min(bx0 + cx, 31);
        int y = min(by0 + cy, 31);
        int z = min(bz0 + cz, 31);
        sgrid[cell * TSTRIDE + t] = g_bgP[((x * 32 + y) * 32 + z) * 16 + t];
    }
    __syncthreads();

    // ---- per-voxel interpolation ----
    int ld = tid & 31;            // gd within tile (coalesced lanes)
    int lw = (tid >> 5) & 3;
    int lh = tid >> 7;

    int gh = gh0 + lh, gw = gw0 + lw, gd = gd0 + ld;
    int idx = (gh << 14) | (gw << 7) | gd;

    // exact reference index/weight math (fp32)
    float x = fminf(fmaxf((float)gh * s, 0.0f), 31.0f);
    float y = fminf(fmaxf((float)gw * s, 0.0f), 31.0f);
    float z = fminf(fmaxf((float)gd * s, 0.0f), 31.0f);

    int x0 = (int)floorf(x);  float fx = x - (float)x0;  int x1 = min(x0 + 1, 31);
    int y0 = (int)floorf(y);  float fy = y - (float)y0;  int y1 = min(y0 + 1, 31);
    int z0 = (int)floorf(z);  float fz = z - (float)z0;  int z1 = min(z0 + 1, 31);

    float g = __ldg(&gm[idx]);
    float t = fminf(fmaxf(g * 15.0f, 0.0f), 15.0f);
    int t0 = (int)floorf(t);  float ft = t - (float)t0;
    __half2 fth2 = __half2half2(__float2half_rn(ft));

    // cell base + deltas (each delta is 0 or the axis stride)
    int cbase = ((x0 - bx0) * 3 + (y0 - by0)) * CZ + (z0 - bz0);
    int dx = (x1 - x0) * 3 * CZ;
    int dy = (y1 - y0) * CZ;
    int dz = (z1 - z0);

    float wx1 = fx, wx0 = 1.0f - fx;
    float wy1 = fy, wy0 = 1.0f - fy;
    float wz1 = fz, wz0 = 1.0f - fz;
    float w00 = wx0 * wy0, w01 = wx0 * wy1, w10 = wx1 * wy0, w11 = wx1 * wy1;

    float wgt[8] = { w00 * wz0, w00 * wz1, w01 * wz0, w01 * wz1,
                     w10 * wz0, w10 * wz1, w11 * wz0, w11 * wz1 };
    int   cof[8] = { cbase,           cbase + dz,
                     cbase + dy,      cbase + dy + dz,
                     cbase + dx,      cbase + dx + dz,
                     cbase + dx + dy, cbase + dx + dy + dz };

    float ax = 0.0f, ay = 0.0f, az = 0.0f, aw = 0.0f;

#pragma unroll
    for (int k = 0; k < 8; k++) {
        uint4 e = sgrid[cof[k] * TSTRIDE + t0];
        __half2 v0lo = *reinterpret_cast<__half2*>(&e.x);
        __half2 v0hi = *reinterpret_cast<__half2*>(&e.y);
        __half2 v1lo = *reinterpret_cast<__half2*>(&e.z);
        __half2 v1hi = *reinterpret_cast<__half2*>(&e.w);
        // fp16 t-lerp: r = v0 + ft*(v1-v0)
        __half2 rlo = __hfma2(fth2, __hsub2(v1lo, v0lo), v0lo);
        __half2 rhi = __hfma2(fth2, __hsub2(v1hi, v0hi), v0hi);
        float2 flo = __half22float2(rlo);
        float2 fhi = __half22float2(rhi);
        float w = wgt[k];
        ax += w * flo.x;
        ay += w * flo.y;
        az += w * fhi.x;
        aw += w * fhi.y;
    }

    out[idx]            = ax;
    out[idx + NVOX]     = ay;
    out[idx + 2 * NVOX] = az;
    out[idx + 3 * NVOX] = aw;
}

extern "C" void kernel_launch(void* const* d_in, const int* in_sizes, int n_in,
                              void* d_out, int out_size) {
    const float* bg = (const float*)d_in[0];
    const float* gm = (const float*)d_in[1];
    float* out = (float*)d_out;

    (void)in_sizes; (void)n_in; (void)out_size;

    bgT_pair_kernel<<<(BG_SPATIAL + 255) / 256, 256>>>(bg);
    bgrid_slice_kernel<<<4096, 512>>>(gm, out);
}

// round 6
// speedup vs baseline: 1.8101x; 1.1107x over previous
#include <cuda_runtime.h>
#include <cuda_fp16.h>
#include <stdint.h>

// bg: (1, 4, 32, 32, 32, 16) float32  -> d_in[0]
// gm: (1, 1, 128, 128, 128) float32   -> d_in[1]
// out: (1, 4, 128, 128, 128) float32

#define UP 16
#define G  128
#define NVOX (G * G * G)                 // 2,097,152
#define BG_SPATIAL (32 * 32 * 32 * 16)   // 524,288

// Paired fp16 grid: entry (x,y,z,t) = 16B {v4[t], v4[t+1] (t+1 clamped)}.
__device__ uint4 g_bgP[BG_SPATIAL];

// ---------------------------------------------------------------------------
// Kernel 1: transpose (c,x,y,z,t) -> paired channel-last fp16.
// t is the fastest dim; __shfl_down(width=16) fetches the t+1 entry
// (lane t=15 keeps its own value = the clamp we need).
// ---------------------------------------------------------------------------
__global__ void bgT_pair_kernel(const float* __restrict__ bg) {
    int idx = blockIdx.x * blockDim.x + threadIdx.x;
    if (idx >= BG_SPATIAL) return;
    float a = __ldg(&bg[0 * BG_SPATIAL + idx]);
    float b = __ldg(&bg[1 * BG_SPATIAL + idx]);
    float c = __ldg(&bg[2 * BG_SPATIAL + idx]);
    float d = __ldg(&bg[3 * BG_SPATIAL + idx]);
    __half2 lo = __floats2half2_rn(a, b);
    __half2 hi = __floats2half2_rn(c, d);
    uint32_t ulo = *reinterpret_cast<uint32_t*>(&lo);
    uint32_t uhi = *reinterpret_cast<uint32_t*>(&hi);
    uint32_t nlo = __shfl_down_sync(0xffffffffu, ulo, 1, 16);
    uint32_t nhi = __shfl_down_sync(0xffffffffu, uhi, 1, 16);
    uint4 e;
    e.x = ulo; e.y = uhi; e.z = nlo; e.w = nhi;
    g_bgP[idx] = e;
}

// ---------------------------------------------------------------------------
// Kernel 2: slice. Tile = 8(gh) x 4(gw) x 32(gd) = 1024 voxels, 512 threads,
// 2 voxels/thread (gh and gh+4). Cells spanned: 4 x 3 x 10 = 120.
// Axis tables (offset/delta/frac) built once per block kill per-voxel
// index math; each corner = 1 IADD + 1 LDS.128.
// ---------------------------------------------------------------------------
#define CX 4
#define CY 3
#define CZ 10
#define NCELLS (CX * CY * CZ)   // 120
#define TSTRIDE 17              // uint4 slots per t-row (bank spread)
#define XSTRIDE (CY * CZ * TSTRIDE)  // 510 slots per x-cell
#define YSTRIDE (CZ * TSTRIDE)       // 170 slots per y-cell

__global__ __launch_bounds__(512)
void bgrid_slice_kernel(const float* __restrict__ gm, float* __restrict__ out) {
    __shared__ uint4 sgrid[NCELLS * TSTRIDE];  // 120*17*16 = 32640 B
    __shared__ int   sOff[44];   // x:0..7  y:8..11  z:12..43
    __shared__ int   sDlt[44];
    __shared__ float sFrc[44];

    int tid = threadIdx.x;
    int bd = blockIdx.x & 3;           // 4 gd tiles of 32
    int bw = (blockIdx.x >> 2) & 31;   // 32 gw tiles of 4
    int bh = blockIdx.x >> 7;          // 16 gh tiles of 8

    int gh0 = bh << 3, gw0 = bw << 2, gd0 = bd << 5;

    const float s = 31.0f / 127.0f;
    int bx0 = (int)floorf((float)gh0 * s);
    int by0 = (int)floorf((float)gw0 * s);
    int bz0 = (int)floorf((float)gd0 * s);

    // ---- axis tables (44 threads) ----
    if (tid < 44) {
        int gcoord, base, stride;
        if (tid < 8)       { gcoord = gh0 + tid;        base = bx0; stride = XSTRIDE; }
        else if (tid < 12) { gcoord = gw0 + (tid - 8);  base = by0; stride = YSTRIDE; }
        else               { gcoord = gd0 + (tid - 12); base = bz0; stride = TSTRIDE; }
        float v = fminf(fmaxf((float)gcoord * s, 0.0f), 31.0f);
        int i0 = (int)floorf(v);
        int i1 = min(i0 + 1, 31);
        sOff[tid] = (i0 - base) * stride;
        sDlt[tid] = (i1 - i0) * stride;
        sFrc[tid] = v - (float)i0;
    }

    // ---- cooperative fill: 120 cells x 16 t entries of 16B ----
    for (int e = tid; e < NCELLS * 16; e += 512) {
        int t    = e & 15;
        int cell = e >> 4;              // (cx*CY+cy)*CZ + cz
        int cz   = cell % CZ;
        int cxy  = cell / CZ;
        int cy   = cxy % CY;
        int cx   = cxy / CY;
        int x = min(bx0 + cx, 31);
        int y = min(by0 + cy, 31);
        int z = min(bz0 + cz, 31);
        sgrid[cell * TSTRIDE + t] = g_bgP[((x * 32 + y) * 32 + z) * 16 + t];
    }
    __syncthreads();

    // ---- per-voxel interpolation: 2 voxels per thread (lh and lh+4) ----
    int ld = tid & 31;
    int lw = (tid >> 5) & 3;
    int lh = tid >> 7;                 // 0..3; second voxel lh+4

    int offY = sOff[8 + lw],  dY = sDlt[8 + lw];  float fy = sFrc[8 + lw];
    int offZ = sOff[12 + ld], dZ = sDlt[12 + ld]; float fz = sFrc[12 + ld];
    float wy0 = 1.0f - fy, wz0 = 1.0f - fz;

    int gw = gw0 + lw, gd = gd0 + ld;
    int idx_base = (gw << 7) | gd;

#pragma unroll
    for (int vv = 0; vv < 2; vv++) {
        int xl = lh + (vv << 2);
        int offX = sOff[xl], dX = sDlt[xl];  float fx = sFrc[xl];
        int gh = gh0 + xl;
        int idx = (gh << 14) | idx_base;

        float g = __ldg(&gm[idx]);
        float t = fminf(fmaxf(g * 15.0f, 0.0f), 15.0f);
        int t0 = (int)floorf(t);
        float ft = t - (float)t0;
        __half2 fth2 = __half2half2(__float2half_rn(ft));

        int b000 = offX + offY + offZ + t0;
        float wx0 = 1.0f - fx;
        float w00 = wx0 * wy0, w01 = wx0 * fy, w10 = fx * wy0, w11 = fx * fy;

        float ax = 0.0f, ay = 0.0f, az = 0.0f, aw = 0.0f;

#pragma unroll
        for (int k = 0; k < 8; k++) {
            int slot = b000 + ((k & 1) ? dZ : 0) + ((k & 2) ? dY : 0) + ((k & 4) ? dX : 0);
            float wxy = (k & 4) ? ((k & 2) ? w11 : w10) : ((k & 2) ? w01 : w00);
            float w   = wxy * ((k & 1) ? fz : wz0);
            uint4 e = sgrid[slot];
            __half2 v0lo = *reinterpret_cast<__half2*>(&e.x);
            __half2 v0hi = *reinterpret_cast<__half2*>(&e.y);
            __half2 v1lo = *reinterpret_cast<__half2*>(&e.z);
            __half2 v1hi = *reinterpret_cast<__half2*>(&e.w);
            __half2 rlo = __hfma2(fth2, __hsub2(v1lo, v0lo), v0lo);
            __half2 rhi = __hfma2(fth2, __hsub2(v1hi, v0hi), v0hi);
            float2 flo = __half22float2(rlo);
            float2 fhi = __half22float2(rhi);
            ax += w * flo.x;
            ay += w * flo.y;
            az += w * fhi.x;
            aw += w * fhi.y;
        }

        out[idx]            = ax;
        out[idx + NVOX]     = ay;
        out[idx + 2 * NVOX] = az;
        out[idx + 3 * NVOX] = aw;
    }
}

extern "C" void kernel_launch(void* const* d_in, const int* in_sizes, int n_in,
                              void* d_out, int out_size) {
    const float* bg = (const float*)d_in[0];
    const float* gm = (const float*)d_in[1];
    float* out = (float*)d_out;

    (void)in_sizes; (void)n_in; (void)out_size;

    bgT_pair_kernel<<<(BG_SPATIAL + 255) / 256, 256>>>(bg);
    bgrid_slice_kernel<<<2048, 512>>>(gm, out);
}

// round 8
// speedup vs baseline: 1.9397x; 1.0716x over previous
#include <cuda_runtime.h>
#include <cuda_fp16.h>
#include <stdint.h>

// bg: (1, 4, 32, 32, 32, 16) float32  -> d_in[0]
// gm: (1, 1, 128, 128, 128) float32   -> d_in[1]
// out: (1, 4, 128, 128, 128) float32

#define UP 16
#define G  128
#define NVOX (G * G * G)                 // 2,097,152
#define BG_SPATIAL (32 * 32 * 32 * 16)   // 524,288

// Delta-paired fp16 grid: entry (x,y,z,t) = 16B {v4[t], v4[t+1]-v4[t]}
// (t+1 clamped to 15 -> delta 0). 8.4 MB static device scratch.
__device__ uint4 g_bgP[BG_SPATIAL];

// ---------------------------------------------------------------------------
// Kernel 1: transpose (c,x,y,z,t) -> delta-paired channel-last fp16.
// ---------------------------------------------------------------------------
__global__ void bgT_pair_kernel(const float* __restrict__ bg) {
    int idx = blockIdx.x * blockDim.x + threadIdx.x;
    if (idx >= BG_SPATIAL) return;
    float a = __ldg(&bg[0 * BG_SPATIAL + idx]);
    float b = __ldg(&bg[1 * BG_SPATIAL + idx]);
    float c = __ldg(&bg[2 * BG_SPATIAL + idx]);
    float d = __ldg(&bg[3 * BG_SPATIAL + idx]);
    __half2 lo = __floats2half2_rn(a, b);
    __half2 hi = __floats2half2_rn(c, d);
    uint32_t ulo = *reinterpret_cast<uint32_t*>(&lo);
    uint32_t uhi = *reinterpret_cast<uint32_t*>(&hi);
    // neighbor (t+1) within 16-lane segment; lane 15 keeps own value (clamp)
    uint32_t nlo = __shfl_down_sync(0xffffffffu, ulo, 1, 16);
    uint32_t nhi = __shfl_down_sync(0xffffffffu, uhi, 1, 16);
    __half2 dlo = __hsub2(*reinterpret_cast<__half2*>(&nlo), lo);
    __half2 dhi = __hsub2(*reinterpret_cast<__half2*>(&nhi), hi);
    uint4 e;
    e.x = ulo; e.y = uhi;
    e.z = *reinterpret_cast<uint32_t*>(&dlo);
    e.w = *reinterpret_cast<uint32_t*>(&dhi);
    g_bgP[idx] = e;
}

// ---------------------------------------------------------------------------
// Kernel 2: slice. Tile = 8(gh) x 8(gw) x 32(gd) = 2048 voxels, 512 threads,
// 4 voxels/thread. Cells spanned: 4 x 4 x 10 = 160.
// Axis LUTs (slot-offset/delta/frac) built once; corner = 1 IADD + 1 LDS.128
// + 2 HFMA2 (t-lerp via stored delta) + cvt + 4 FFMA.
// ---------------------------------------------------------------------------
#define CX 4
#define CY 4
#define CZ 10
#define NCELLS (CX * CY * CZ)        // 160
#define TSTRIDE 17                   // uint4 slots per t-row (bank spread)
#define YSTRIDE (CZ * TSTRIDE)       // 170
#define XSTRIDE (CY * YSTRIDE)       // 680

__global__ __launch_bounds__(512)
void bgrid_slice_kernel(const float* __restrict__ gm, float* __restrict__ out) {
    __shared__ uint4 sgrid[NCELLS * TSTRIDE];  // 160*17*16 = 43520 B
    __shared__ int   sOff[48];   // x:0..7  y:8..15  z:16..47
    __shared__ int   sDlt[48];
    __shared__ float sFrc[48];

    int tid = threadIdx.x;
    int bd = blockIdx.x & 3;           // 4 gd tiles of 32
    int bw = (blockIdx.x >> 2) & 15;   // 16 gw tiles of 8
    int bh = blockIdx.x >> 6;          // 16 gh tiles of 8

    int gh0 = bh << 3, gw0 = bw << 3, gd0 = bd << 5;

    const float s = 31.0f / 127.0f;
    int bx0 = (int)floorf((float)gh0 * s);
    int by0 = (int)floorf((float)gw0 * s);
    int bz0 = (int)floorf((float)gd0 * s);

    // ---- axis tables (48 threads) ----
    if (tid < 48) {
        int gcoord, base, stride;
        if (tid < 8)       { gcoord = gh0 + tid;        base = bx0; stride = XSTRIDE; }
        else if (tid < 16) { gcoord = gw0 + (tid - 8);  base = by0; stride = YSTRIDE; }
        else               { gcoord = gd0 + (tid - 16); base = bz0; stride = TSTRIDE; }
        float v = fminf(fmaxf((float)gcoord * s, 0.0f), 31.0f);
        int i0 = (int)floorf(v);
        int i1 = min(i0 + 1, 31);
        sOff[tid] = (i0 - base) * stride;
        sDlt[tid] = (i1 - i0) * stride;
        sFrc[tid] = v - (float)i0;
    }

    // ---- cooperative fill: 160 cells x 16 t entries of 16B (5 iters) ----
#pragma unroll
    for (int it = 0; it < 5; it++) {
        int e    = tid + it * 512;
        int t    = e & 15;
        int cell = e >> 4;              // (cx*CY+cy)*CZ + cz
        int cz   = cell % CZ;
        int cxy  = cell / CZ;
        int cy   = cxy & 3;
        int cx   = cxy >> 2;
        int x = min(bx0 + cx, 31);
        int y = min(by0 + cy, 31);
        int z = min(bz0 + cz, 31);
        sgrid[cell * TSTRIDE + t] = g_bgP[((x * 32 + y) * 32 + z) * 16 + t];
    }
    __syncthreads();

    // ---- 4 voxels/thread: (lh2 + 4a, lw2 + 4b, ld) ----
    int ld  = tid & 31;
    int lw2 = (tid >> 5) & 3;
    int lh2 = tid >> 7;               // 0..3

    int offZ = sOff[16 + ld], dZ = sDlt[16 + ld]; float fz = sFrc[16 + ld];
    float wz0 = 1.0f - fz;
    int gd = gd0 + ld;

    // prefetch gm for all 4 voxels
    int   vidx[4];
    float gv[4];
#pragma unroll
    for (int v = 0; v < 4; v++) {
        int xl = lh2 + ((v >> 1) << 2);
        int yl = lw2 + ((v & 1) << 2);
        vidx[v] = ((gh0 + xl) << 14) | ((gw0 + yl) << 7) | gd;
        gv[v] = __ldg(&gm[vidx[v]]);
    }

#pragma unroll
    for (int v = 0; v < 4; v++) {
        int xl = lh2 + ((v >> 1) << 2);
        int yl = lw2 + ((v & 1) << 2);
        int offX = sOff[xl],     dX = sDlt[xl];      float fx = sFrc[xl];
        int offY = sOff[8 + yl], dY = sDlt[8 + yl];  float fy = sFrc[8 + yl];

        float t = fminf(fmaxf(gv[v] * 15.0f, 0.0f), 15.0f);
        int t0 = (int)floorf(t);
        float ft = t - (float)t0;
        __half2 fth2 = __half2half2(__float2half_rn(ft));

        int b000 = offX + offY + offZ + t0;

        float wx0 = 1.0f - fx, wy0 = 1.0f - fy;
        float w00 = wx0 * wy0, w01 = wx0 * fy, w10 = fx * wy0, w11 = fx * fy;
        float wgt[8] = { w00 * wz0, w00 * fz, w01 * wz0, w01 * fz,
                         w10 * wz0, w10 * fz, w11 * wz0, w11 * fz };

        float ax = 0.0f, ay = 0.0f, az = 0.0f, aw = 0.0f;

#pragma unroll
        for (int k = 0; k < 8; k++) {
            int slot = b000 + ((k & 1) ? dZ : 0) + ((k & 2) ? dY : 0) + ((k & 4) ? dX : 0);
            uint4 e = sgrid[slot];
            __half2 v0lo = *reinterpret_cast<__half2*>(&e.x);
            __half2 v0hi = *reinterpret_cast<__half2*>(&e.y);
            __half2 dlo  = *reinterpret_cast<__half2*>(&e.z);
            __half2 dhi  = *reinterpret_cast<__half2*>(&e.w);
            // t-lerp via stored delta: r = v0 + ft*d
            __half2 rlo = __hfma2(fth2, dlo, v0lo);
            __half2 rhi = __hfma2(fth2, dhi, v0hi);
            float2 flo = __half22float2(rlo);
            float2 fhi = __half22float2(rhi);
            float w = wgt[k];
            ax += w * flo.x;
            ay += w * flo.y;
            az += w * fhi.x;
            aw += w * fhi.y;
        }

        out[vidx[v]]            = ax;
        out[vidx[v] + NVOX]     = ay;
        out[vidx[v] + 2 * NVOX] = az;
        out[vidx[v] + 3 * NVOX] = aw;
    }
}

extern "C" void kernel_launch(void* const* d_in, const int* in_sizes, int n_in,
                              void* d_out, int out_size) {
    const float* bg = (const float*)d_in[0];
    const float* gm = (const float*)d_in[1];
    float* out = (float*)d_out;

    (void)in_sizes; (void)n_in; (void)out_size;

    bgT_pair_kernel<<<(BG_SPATIAL + 255) / 256, 256>>>(bg);
    bgrid_slice_kernel<<<1024, 512>>>(gm, out);
}